// round 13
// baseline (speedup 1.0000x reference)
#include <cuda_runtime.h>
#include <cuda_bf16.h>
#include <cstdint>

typedef unsigned long long u64;

#define B_      32
#define QL      4
#define DIM     2048
#define HEADS   16
#define HD      128
#define KVL     8192
#define M_      (B_*QL)
#define NQKV    2304
#define NSPLIT  8                /* split-K for projections + effective attn splits */
#define ASPL    4                /* attention KV splits (x2 warp-groups = 8 eff)    */
#define CHUNKA  (KVL/ASPL)       /* 2048 keys per CTA      */
#define NTA     (CHUNKA/64)      /* 32 tiles of 64 keys    */
#define SCALE   0.08838834764831845f
#define SMAX    16.0f

/* ------------------------------------------------------------------ */
__device__ float g_part[NSPLIT * M_ * NQKV];
__device__ float g_qkv [M_ * NQKV];
__device__ float g_po  [(size_t)B_ * 64 * NSPLIT * HD];
__device__ float g_pml [B_ * 64 * NSPLIT * 2];
__device__ float g_o   [M_ * DIM];

/* ---------------- packed f32x2 (projection GEMMs) ------------------ */
__device__ __forceinline__ u64 pack2(float x) {
    u64 r; asm("mov.b64 %0, {%1, %1};" : "=l"(r) : "f"(x)); return r;
}
__device__ __forceinline__ void fma2(u64& d, u64 a, u64 b) {
    asm("fma.rn.f32x2 %0, %1, %2, %0;" : "+l"(d) : "l"(a), "l"(b));
}
__device__ __forceinline__ float2 unpk(u64 v) {
    float2 f; asm("mov.b64 {%0, %1}, %2;" : "=f"(f.x), "=f"(f.y) : "l"(v)); return f;
}

/* ---------------- mma.sync helpers -------------------------------- */
__device__ __forceinline__ void ldsm_x4(uint32_t* a, uint32_t addr) {
    asm volatile("ldmatrix.sync.aligned.m8n8.x4.shared.b16 {%0,%1,%2,%3}, [%4];"
        : "=r"(a[0]), "=r"(a[1]), "=r"(a[2]), "=r"(a[3]) : "r"(addr));
}
__device__ __forceinline__ void ldsm_x4t(uint32_t* a, uint32_t addr) {
    asm volatile("ldmatrix.sync.aligned.m8n8.x4.trans.shared.b16 {%0,%1,%2,%3}, [%4];"
        : "=r"(a[0]), "=r"(a[1]), "=r"(a[2]), "=r"(a[3]) : "r"(addr));
}
__device__ __forceinline__ void mma_bf16(float* c, const uint32_t* a,
                                         uint32_t b0, uint32_t b1) {
    asm volatile("mma.sync.aligned.m16n8k16.row.col.f32.bf16.bf16.f32 "
        "{%0,%1,%2,%3}, {%4,%5,%6,%7}, {%8,%9}, {%0,%1,%2,%3};"
        : "+f"(c[0]), "+f"(c[1]), "+f"(c[2]), "+f"(c[3])
        : "r"(a[0]), "r"(a[1]), "r"(a[2]), "r"(a[3]), "r"(b0), "r"(b1));
}

__device__ __forceinline__ uint32_t bfpair(float a, float b) {
    __nv_bfloat162 t = __floats2bfloat162_rn(a, b);
    return *(uint32_t*)&t;
}
__device__ __forceinline__ uint32_t hipair(float a, float b, uint32_t& lo) {
    __nv_bfloat16 ha = __float2bfloat16(a), hb = __float2bfloat16(b);
    lo = bfpair(a - __bfloat162float(ha), b - __bfloat162float(hb));
    __nv_bfloat162 h; h.x = ha; h.y = hb;
    return *(uint32_t*)&h;
}

/* ------------------------------------------------------------------ */
/* Projection GEMM (unchanged)                                         */
/* ------------------------------------------------------------------ */
__global__ __launch_bounds__(256) void gemm64(
    const float* __restrict__ A, int lda,
    const float* __restrict__ B, int ldb,
    int ncol0)
{
    __shared__ u64   sA2[16][65];
    __shared__ float sB[16][64];

    const int tid = threadIdx.x;
    const int tx  = tid & 15, ty = tid >> 4;
    const int m0  = blockIdx.y * 64, n0 = blockIdx.x * 64;
    const int k0  = blockIdx.z * 256;

    u64 acc[4][2];
#pragma unroll
    for (int i = 0; i < 4; i++) { acc[i][0] = 0ull; acc[i][1] = 0ull; }

    const int ar = tid >> 2, akq = tid & 3;
    const int bk = tid >> 4, bc  = tid & 15;

    for (int kt = 0; kt < 256; kt += 16) {
        float4 av = *(const float4*)&A[(size_t)(m0 + ar) * lda + k0 + kt + akq * 4];
        float4 bv = *(const float4*)&B[(size_t)(k0 + kt + bk) * ldb + n0 + bc * 4];
        __syncthreads();
        sA2[akq * 4 + 0][ar] = pack2(av.x);
        sA2[akq * 4 + 1][ar] = pack2(av.y);
        sA2[akq * 4 + 2][ar] = pack2(av.z);
        sA2[akq * 4 + 3][ar] = pack2(av.w);
        *(float4*)&sB[bk][bc * 4] = bv;
        __syncthreads();
#pragma unroll
        for (int kk = 0; kk < 16; kk++) {
            ulonglong2 b2 = *(const ulonglong2*)&sB[kk][tx * 4];
#pragma unroll
            for (int i = 0; i < 4; i++) {
                u64 a2 = sA2[kk][ty * 4 + i];
                fma2(acc[i][0], a2, b2.x);
                fma2(acc[i][1], a2, b2.y);
            }
        }
    }

    float* dst = g_part + (size_t)(blockIdx.z * M_ + m0) * NQKV + ncol0 + n0;
#pragma unroll
    for (int i = 0; i < 4; i++) {
        float2 f0 = unpk(acc[i][0]), f1 = unpk(acc[i][1]);
        *(float4*)&dst[(size_t)(ty * 4 + i) * NQKV + tx * 4] =
            make_float4(f0.x, f0.y, f1.x, f1.y);
    }
}

__global__ void reduce_qkv(const float* __restrict__ bq,
                           const float* __restrict__ bk,
                           const float* __restrict__ bv)
{
    int idx = blockIdx.x * 256 + threadIdx.x;
    if (idx >= M_ * NQKV / 4) return;
    int m = idx / (NQKV / 4);
    int n = (idx % (NQKV / 4)) * 4;
    float4 s = make_float4(0.f, 0.f, 0.f, 0.f);
#pragma unroll
    for (int sk = 0; sk < NSPLIT; sk++) {
        float4 v = *(const float4*)&g_part[(size_t)(sk * M_ + m) * NQKV + n];
        s.x += v.x; s.y += v.y; s.z += v.z; s.w += v.w;
    }
    float4 bb;
    if (n < 2048)       bb = *(const float4*)&bq[n];
    else if (n < 2176)  bb = *(const float4*)&bk[n - 2048];
    else                bb = *(const float4*)&bv[n - 2176];
    s.x += bb.x; s.y += bb.y; s.z += bb.z; s.w += bb.w;
    *(float4*)&g_qkv[(size_t)m * NQKV + n] = s;
}

/* ------------------------------------------------------------------ */
/* attn5: warp-group pipelined mma.sync attention, FULL hi/lo numerics */
/*  grid (ASPL, B), 256 threads = 2 groups of 4 warps                  */
/*  group (t&1) computes tile t; other group loads tile t+1            */
/*  S = QhKh+QlKh+QhKl ; O = PhVh+PlVh+PhVl  (384 MMA/warp/tile)       */
/*  smem 160KB: Qh|Ql | Kh[2]|Kl[2] | Vh[2]|Vl[2]  (16KB tiles)        */
/* ------------------------------------------------------------------ */
#define OQH5 0
#define OQL5 16384
#define OKH5 32768       /* 2 x 16384 */
#define OKL5 65536       /* 2 x 16384 */
#define OVH5 98304       /* 2 x 16384 */
#define OVL5 131072      /* 2 x 16384 */
#define SMEM5 163840

__global__ __launch_bounds__(256, 1) void attn5(
    const float* __restrict__ bias,
    const float* __restrict__ cache_k,
    const float* __restrict__ cache_v)
{
    extern __shared__ char smem[];
    const uint32_t sb = (uint32_t)__cvta_generic_to_shared(smem);
    const int tid  = threadIdx.x;
    const int lane = tid & 31, wid = tid >> 5;
    const int grp  = wid >> 2;            /* warp-group 0 / 1          */
    const int wg   = wid & 3;             /* warp within group         */
    const int s    = blockIdx.x, b = blockIdx.y;
    const int gq   = lane >> 2, tig = lane & 3;
    const int wr0  = wg * 16;

    /* loader mapping (within a 128-thread group) */
    const int ltid = tid & 127;
    const int jr = ltid >> 1;             /* key row 0..63 */
    const int e0 = (ltid & 1) * 64;
    const uint32_t rb = (uint32_t)(jr * 256);
    const uint32_t sx = ((uint32_t)jr & 7u) << 4;

    /* ---- Q -> smem hi/lo (all 256 threads), SCALE folded ---- */
    {
        const int qr = tid >> 2;          /* 0..63 */
        const int e0q = (tid & 3) * 32;
        const uint32_t qrb = (uint32_t)(qr * 256);
        const uint32_t qsx = ((uint32_t)qr & 7u) << 4;
        const float* qp = &g_qkv[(size_t)(b * QL + (qr & 3)) * NQKV + (qr >> 2) * HD + e0q];
#pragma unroll
        for (int i = 0; i < 8; i++) {
            float4 q4 = *(const float4*)&qp[4 * i];
            q4.x *= SCALE; q4.y *= SCALE; q4.z *= SCALE; q4.w *= SCALE;
            uint32_t off = qrb + (((uint32_t)(2 * (e0q + 4 * i))) ^ qsx);
            uint32_t l01, l23;
            uint32_t h01 = hipair(q4.x, q4.y, l01);
            uint32_t h23 = hipair(q4.z, q4.w, l23);
            *(uint2*)(smem + OQH5 + off) = make_uint2(h01, h23);
            *(uint2*)(smem + OQL5 + off) = make_uint2(l01, l23);
        }
    }

    /* ---- prologue: group 0 loads tile 0 into buf 0 (hi/lo) ---- */
    if (grp == 0) {
        int jg = s * CHUNKA + jr;
        const float *srck, *srcv;
        if (jg < KVL - QL) {
            size_t off = ((size_t)b * KVL + jg + QL) * HD + e0;
            srck = cache_k + off; srcv = cache_v + off;
        } else {
            size_t mrow = (size_t)(b * QL + (jg - (KVL - QL))) * NQKV;
            srck = g_qkv + mrow + 2048 + e0;
            srcv = g_qkv + mrow + 2176 + e0;
        }
#pragma unroll
        for (int i = 0; i < 16; i++) {
            float4 k4 = *(const float4*)&srck[4 * i];
            float4 v4 = *(const float4*)&srcv[4 * i];
            uint32_t off = rb + (((uint32_t)(2 * (e0 + 4 * i))) ^ sx);
            uint32_t kl01, kl23, vl01, vl23;
            uint32_t kh01 = hipair(k4.x, k4.y, kl01);
            uint32_t kh23 = hipair(k4.z, k4.w, kl23);
            uint32_t vh01 = hipair(v4.x, v4.y, vl01);
            uint32_t vh23 = hipair(v4.z, v4.w, vl23);
            *(uint2*)(smem + OKH5 + off) = make_uint2(kh01, kh23);
            *(uint2*)(smem + OKL5 + off) = make_uint2(kl01, kl23);
            *(uint2*)(smem + OVH5 + off) = make_uint2(vh01, vh23);
            *(uint2*)(smem + OVL5 + off) = make_uint2(vl01, vl23);
        }
    }

    float oacc[16][4];
#pragma unroll
    for (int n = 0; n < 16; n++)
#pragma unroll
        for (int c = 0; c < 4; c++) oacc[n][c] = 0.f;
    float lacc0 = 0.f, lacc1 = 0.f;

    const size_t brow0 = ((size_t)b * 64 + wr0 + gq) * KVL;

    for (int t = 0; t < NTA; t++) {
        __syncthreads();
        if (grp == (t & 1)) {
            /* =================== COMPUTE tile t =================== */
            const int kb = s * CHUNKA + t * 64;
            const uint32_t buf = (uint32_t)(t & 1) * 16384;
            const uint32_t khb = sb + OKH5 + buf;
            const uint32_t klb = sb + OKL5 + buf;
            const uint32_t vhb = sb + OVH5 + buf;
            const uint32_t vlb = sb + OVL5 + buf;

            /* bias (LDG issued early, consumed after S-mma) */
            float2 bA[8], bB[8];
#pragma unroll
            for (int n = 0; n < 8; n++) {
                bA[n] = *(const float2*)&bias[brow0 + kb + n * 8 + 2 * tig];
                bB[n] = *(const float2*)&bias[brow0 + 8 * KVL + kb + n * 8 + 2 * tig];
            }

            float sacc[8][4];
#pragma unroll
            for (int n = 0; n < 8; n++)
#pragma unroll
                for (int c = 0; c < 4; c++) sacc[n][c] = 0.f;

            /* ---- S = Qh Kh + Ql Kh + Qh Kl ---- */
#pragma unroll
            for (int e = 0; e < 8; e++) {
                const uint32_t cb = (uint32_t)(e * 32);
                const int arow = wr0 + (lane & 15);
                uint32_t aoff = (uint32_t)(arow * 256)
                    + ((cb + (uint32_t)((lane >> 4) << 4)) ^ (((uint32_t)arow & 7u) << 4));
                uint32_t aqh[4], aql[4];
                ldsm_x4(aqh, sb + OQH5 + aoff);
                ldsm_x4(aql, sb + OQL5 + aoff);
#pragma unroll
                for (int np = 0; np < 4; np++) {
                    const int krow = np * 16 + ((lane >> 4) & 1) * 8 + (lane & 7);
                    uint32_t koff = (uint32_t)(krow * 256)
                        + (((uint32_t)(cb + ((lane >> 3) & 1) * 16)) ^ (((uint32_t)krow & 7u) << 4));
                    uint32_t bh[4], bl[4];
                    ldsm_x4(bh, khb + koff);
                    ldsm_x4(bl, klb + koff);
                    mma_bf16(sacc[2*np],   aqh, bh[0], bh[1]);
                    mma_bf16(sacc[2*np+1], aqh, bh[2], bh[3]);
                    mma_bf16(sacc[2*np],   aql, bh[0], bh[1]);
                    mma_bf16(sacc[2*np+1], aql, bh[2], bh[3]);
                    mma_bf16(sacc[2*np],   aqh, bl[0], bl[1]);
                    mma_bf16(sacc[2*np+1], aqh, bl[2], bl[3]);
                }
            }

            /* ---- softmax (fixed shift) + O += Ph Vh + Pl Vh + Ph Vl ---- */
#pragma unroll
            for (int kk = 0; kk < 4; kk++) {
                uint32_t pah[4], pal[4];
#pragma unroll
                for (int h = 0; h < 2; h++) {
                    const int n = 2 * kk + h;
                    float p0 = __expf(sacc[n][0] + bA[n].x - SMAX);
                    float p1 = __expf(sacc[n][1] + bA[n].y - SMAX);
                    float p2 = __expf(sacc[n][2] + bB[n].x - SMAX);
                    float p3 = __expf(sacc[n][3] + bB[n].y - SMAX);
                    lacc0 += p0 + p1;
                    lacc1 += p2 + p3;
                    pah[2*h]   = hipair(p0, p1, pal[2*h]);
                    pah[2*h+1] = hipair(p2, p3, pal[2*h+1]);
                }
#pragma unroll
                for (int np = 0; np < 8; np++) {
                    const int vrow = kk * 16 + ((lane >> 3) & 1) * 8 + (lane & 7);
                    uint32_t voff = (uint32_t)(vrow * 256)
                        + (((uint32_t)(np * 32 + ((lane >> 4) & 1) * 16)) ^ (((uint32_t)vrow & 7u) << 4));
                    uint32_t vh[4], vl[4];
                    ldsm_x4t(vh, vhb + voff);
                    ldsm_x4t(vl, vlb + voff);
                    mma_bf16(oacc[2*np],   pah, vh[0], vh[1]);
                    mma_bf16(oacc[2*np+1], pah, vh[2], vh[3]);
                    mma_bf16(oacc[2*np],   pal, vh[0], vh[1]);
                    mma_bf16(oacc[2*np+1], pal, vh[2], vh[3]);
                    mma_bf16(oacc[2*np],   pah, vl[0], vl[1]);
                    mma_bf16(oacc[2*np+1], pah, vl[2], vl[3]);
                }
            }
        } else if (t + 1 < NTA) {
            /* =================== LOAD tile t+1 =================== */
            const int tn = t + 1;
            const uint32_t buf = (uint32_t)(tn & 1) * 16384;
            char* khd = smem + OKH5 + buf;
            char* kld = smem + OKL5 + buf;
            char* vhd = smem + OVH5 + buf;
            char* vld = smem + OVL5 + buf;
            int jg = s * CHUNKA + tn * 64 + jr;
            const float *srck, *srcv;
            if (jg < KVL - QL) {
                size_t off = ((size_t)b * KVL + jg + QL) * HD + e0;
                srck = cache_k + off; srcv = cache_v + off;
            } else {
                size_t mrow = (size_t)(b * QL + (jg - (KVL - QL))) * NQKV;
                srck = g_qkv + mrow + 2048 + e0;
                srcv = g_qkv + mrow + 2176 + e0;
            }
#pragma unroll
            for (int i = 0; i < 16; i++) {
                float4 k4 = *(const float4*)&srck[4 * i];
                float4 v4 = *(const float4*)&srcv[4 * i];
                uint32_t off = rb + (((uint32_t)(2 * (e0 + 4 * i))) ^ sx);
                uint32_t kl01, kl23, vl01, vl23;
                uint32_t kh01 = hipair(k4.x, k4.y, kl01);
                uint32_t kh23 = hipair(k4.z, k4.w, kl23);
                uint32_t vh01 = hipair(v4.x, v4.y, vl01);
                uint32_t vh23 = hipair(v4.z, v4.w, vl23);
                *(uint2*)(khd + off) = make_uint2(kh01, kh23);
                *(uint2*)(kld + off) = make_uint2(kl01, kl23);
                *(uint2*)(vhd + off) = make_uint2(vh01, vh23);
                *(uint2*)(vld + off) = make_uint2(vl01, vl23);
            }
        }
    }

    /* ---- epilogue: unnormalized partial O + row sums ---- */
    {
        const int esp  = s * 2 + grp;     /* effective split 0..7 */
        const int row0 = b * 64 + wr0 + gq;
#pragma unroll
        for (int n = 0; n < 16; n++) {
            int col = n * 8 + 2 * tig;
            *(float2*)&g_po[((size_t)row0 * NSPLIT + esp) * HD + col] =
                make_float2(oacc[n][0], oacc[n][1]);
            *(float2*)&g_po[((size_t)(row0 + 8) * NSPLIT + esp) * HD + col] =
                make_float2(oacc[n][2], oacc[n][3]);
        }
        lacc0 += __shfl_xor_sync(0xffffffffu, lacc0, 1);
        lacc0 += __shfl_xor_sync(0xffffffffu, lacc0, 2);
        lacc1 += __shfl_xor_sync(0xffffffffu, lacc1, 1);
        lacc1 += __shfl_xor_sync(0xffffffffu, lacc1, 2);
        if (tig == 0) {
            g_pml[row0 * NSPLIT + esp]       = lacc0;
            g_pml[(row0 + 8) * NSPLIT + esp] = lacc1;
        }
    }
}

/* ------------------------------------------------------------------ */
__global__ void combine2()
{
    int b = blockIdx.x, tid = threadIdx.x;   /* 128 threads */
    int r = tid >> 1, half = tid & 1;
    float lt = 0.f;
#pragma unroll
    for (int s = 0; s < NSPLIT; s++) lt += g_pml[(b * 64 + r) * NSPLIT + s];
    float inv = 1.f / lt;
    int q = r & 3, h = r >> 2;
    float* dst = g_o + (size_t)(b * QL + q) * DIM + h * HD + half * 64;
    size_t pb = ((size_t)(b * 64 + r) * NSPLIT) * HD + half * 64;
    for (int e = 0; e < 64; e += 4) {
        float4 acc = make_float4(0.f, 0.f, 0.f, 0.f);
#pragma unroll
        for (int s = 0; s < NSPLIT; s++) {
            float4 v = *(const float4*)&g_po[pb + (size_t)s * HD + e];
            acc.x += v.x; acc.y += v.y; acc.z += v.z; acc.w += v.w;
        }
        acc.x *= inv; acc.y *= inv; acc.z *= inv; acc.w *= inv;
        *(float4*)&dst[e] = acc;
    }
}

/* ------------------------------------------------------------------ */
__global__ void reduce_out(const float* __restrict__ bo, float* __restrict__ out)
{
    int idx = blockIdx.x * 256 + threadIdx.x;
    int m = idx >> 9;
    int n = (idx & 511) << 2;
    float4 s = *(const float4*)&bo[n];
#pragma unroll
    for (int sk = 0; sk < NSPLIT; sk++) {
        float4 v = *(const float4*)&g_part[(size_t)(sk * M_ + m) * NQKV + n];
        s.x += v.x; s.y += v.y; s.z += v.z; s.w += v.w;
    }
    *(float4*)&out[(size_t)m * DIM + n] = s;
}

/* ------------------------------------------------------------------ */
extern "C" void kernel_launch(void* const* d_in, const int* in_sizes, int n_in,
                              void* d_out, int out_size)
{
    const float* x         = (const float*)d_in[0];
    const float* attn_bias = (const float*)d_in[1];
    const float* cache_k   = (const float*)d_in[2];
    const float* cache_v   = (const float*)d_in[3];
    const float* wq        = (const float*)d_in[4];
    const float* bq        = (const float*)d_in[5];
    const float* wk        = (const float*)d_in[6];
    const float* bk        = (const float*)d_in[7];
    const float* wv        = (const float*)d_in[8];
    const float* bv        = (const float*)d_in[9];
    const float* wo        = (const float*)d_in[10];
    const float* bo        = (const float*)d_in[11];
    float*       out       = (float*)d_out;

    cudaFuncSetAttribute(attn5,
                         cudaFuncAttributeMaxDynamicSharedMemorySize, SMEM5);

    float* go_ptr = nullptr;
    cudaGetSymbolAddress((void**)&go_ptr, g_o);

    /* 1) QKV projections */
    gemm64<<<dim3(32, 2, NSPLIT), 256>>>(x, DIM, wq, 2048, 0);
    gemm64<<<dim3(2, 2, NSPLIT), 256>>>(x, DIM, wk, 128, 2048);
    gemm64<<<dim3(2, 2, NSPLIT), 256>>>(x, DIM, wv, 128, 2176);
    reduce_qkv<<<288, 256>>>(bq, bk, bv);

    /* 2) tensor-core flash attention, warp-group pipelined, full hi/lo */
    attn5<<<dim3(ASPL, B_), 256, SMEM5>>>(attn_bias, cache_k, cache_v);

    /* 3) combine splits */
    combine2<<<B_, 128>>>();

    /* 4) output projection */
    gemm64<<<dim3(32, 2, NSPLIT), 256>>>(go_ptr, DIM, wo, DIM, 0);
    reduce_out<<<256, 256>>>(bo, out);
}